// round 13
// baseline (speedup 1.0000x reference)
#include <cuda_runtime.h>
#include <stdint.h>

#define BNUM 32
#define PNUM 8732
#define CFG  20
#define NPAIR (BNUM*CFG)
#define KPRE 256
#define TOPK 200
#define CAP  2048
#define QCAP 1024
#define NT   256

typedef unsigned long long u64;

// ------------------------------------------------------------------
__device__ uint32_t g_keys[(size_t)NPAIR * PNUM];   // mono(prob) per [b][c][p] (fallback only)
__device__ u64      g_list[(size_t)NPAIR * CAP];    // speculative candidate lists
__device__ uint32_t g_cnt[NPAIR];                   // list counters (zeroed by topk epilogue)

__device__ __forceinline__ uint32_t mono(float f) {
    uint32_t u = __float_as_uint(f);
    return (u & 0x80000000u) ? ~u : (u | 0x80000000u);
}
__device__ __forceinline__ float unmono(uint32_t k) {
    uint32_t u = (k & 0x80000000u) ? (k ^ 0x80000000u) : ~k;
    return __uint_as_float(u);
}

// fixed speculative threshold: prob 0.10 (P(key>=T) ~ 10% per pair for this workload;
// any pair outside [KPRE, CAP] takes the exact global fallback in topk)
#define T_FIXED 0xBDCCCCCDu   // mono(0.10f) = __float_as_uint(0.10f) | 0x80000000

// ------------------------------------------------------------------
// kernel 1: softmax (exact jax.nn.softmax order) -> mono keys + speculative push
// ------------------------------------------------------------------
__global__ void prep_kernel(const float* __restrict__ conf) {
    int g = blockIdx.x * blockDim.x + threadIdx.x;
    if (g >= BNUM * PNUM) return;
    int b = g / PNUM, p = g % PNUM;

    const float* cp = conf + (size_t)g * 21;
    float x[21];
#pragma unroll
    for (int c = 0; c < 21; c++) x[c] = cp[c];
    float m = x[0];
#pragma unroll
    for (int c = 1; c < 21; c++) m = fmaxf(m, x[c]);
    float e[21];
    float s = 0.f;
#pragma unroll
    for (int c = 0; c < 21; c++) { e[c] = expf(x[c] - m); s += e[c]; }
#pragma unroll
    for (int c = 1; c < 21; c++) {
        uint32_t k = mono(e[c] / s);
        int pairIdx = b * CFG + (c - 1);
        g_keys[(size_t)pairIdx * PNUM + p] = k;
        if (k >= T_FIXED) {
            uint32_t pos = atomicAdd(&g_cnt[pairIdx], 1u);
            if (pos < CAP)
                g_list[(size_t)pairIdx * CAP + pos] =
                    ((u64)k << 32) | (uint32_t)(~(uint32_t)p);
        }
    }
}

// ------------------------------------------------------------------
// warp 0 helpers (called by all 32 lanes of warp 0)
// ------------------------------------------------------------------
__device__ __forceinline__ void warp_select(const uint32_t* s_hist,
                                            const uint32_t* s_csum,
                                            uint32_t target, uint32_t n0,
                                            volatile uint32_t* s_sel) {
    const int l = threadIdx.x;
    uint32_t v[8]; uint32_t tot = 0;
#pragma unroll
    for (int m = 0; m < 8; m++) { v[m] = s_csum[l * 8 + m]; tot += v[m]; }
    uint32_t incl = tot;
#pragma unroll
    for (int o = 1; o < 32; o <<= 1) {
        uint32_t t = __shfl_down_sync(0xFFFFFFFFu, incl, o);
        if (l + o < 32) incl += t;
    }
    uint32_t above = incl - tot;
    if ((above + n0 < target) && (incl + n0 >= target)) {
        uint32_t acc = above + n0;
        int mm = 0;
        for (int m = 7; m >= 0; m--) {
            if (acc + v[m] >= target) { mm = m; break; }
            acc += v[m];
        }
        int chunk = l * 8 + mm;
        int bb = chunk * 8;
        for (int bi = chunk * 8 + 7; bi >= chunk * 8; bi--) {
            uint32_t h = s_hist[bi];
            if (acc + h >= target) { bb = bi; break; }
            acc += h;
        }
        s_sel[0] = (uint32_t)bb; s_sel[1] = acc;
    }
}

__device__ __forceinline__ void warp_select256(const uint32_t* s_hist,
                                               uint32_t target, uint32_t n0,
                                               volatile uint32_t* s_sel) {
    const int l = threadIdx.x;
    uint32_t v[8]; uint32_t tot = 0;
#pragma unroll
    for (int m = 0; m < 8; m++) { v[m] = s_hist[l * 8 + m]; tot += v[m]; }
    uint32_t incl = tot;
#pragma unroll
    for (int o = 1; o < 32; o <<= 1) {
        uint32_t t = __shfl_down_sync(0xFFFFFFFFu, incl, o);
        if (l + o < 32) incl += t;
    }
    uint32_t above = incl - tot;
    if ((above + n0 < target) && (incl + n0 >= target)) {
        uint32_t acc = above + n0;
        int bb = l * 8;
        for (int m = 7; m >= 0; m--) {
            if (acc + v[m] >= target) { bb = l * 8 + m; break; }
            acc += v[m];
        }
        s_sel[0] = (uint32_t)bb; s_sel[1] = acc;
    }
}

// ------------------------------------------------------------------
// kernel 2: per (b,c) pair
// ------------------------------------------------------------------
__global__ __launch_bounds__(NT) void topk_nms_kernel(float* __restrict__ out,
                                                      const float* __restrict__ loc,
                                                      const float* __restrict__ prior) {
    __shared__ u64      s_h64[1024];     // hist(2048 u32) / compacted / supp matrix
    __shared__ uint32_t s_csum[256];
    __shared__ u64      s_cand[CAP];
    __shared__ u64      s_key[KPRE];
    __shared__ float4   s_box[KPRE];
    __shared__ float    s_area[KPRE];
    __shared__ uint32_t s_keep[8];
    __shared__ uint32_t s_wpre[8];
    __shared__ uint32_t s_rowmask[8];
    __shared__ uint32_t s_sel[2];
    __shared__ uint32_t s_cnt;
    uint32_t* s_hist = (uint32_t*)s_h64;

    const int pair = blockIdx.x;
    const int b    = pair / CFG;
    const int tid  = threadIdx.x;
    const int wid  = tid >> 5, lane = tid & 31;
    const uint32_t* __restrict__ keys = g_keys + (size_t)pair * PNUM;
    const uint4* __restrict__ keys4 = (const uint4*)keys;
    const int N4 = PNUM / 4;  // 2183

    // ============ candidate set: speculative list from prep (fast path) ============
    uint32_t M = g_cnt[pair];
    if (M >= KPRE && M <= CAP) {
        const u64* __restrict__ lst = g_list + (size_t)pair * CAP;
        for (uint32_t i = tid; i < M; i += NT) s_cand[i] = lst[i];
        __syncthreads();
    } else {
        // ============ exact global select fallback (rare / adversarial data) ============
        {   // zero 2048 u32 = 512 uint4
            uint4* hz = (uint4*)s_hist;
            hz[tid] = make_uint4(0, 0, 0, 0);
            hz[tid + 256] = make_uint4(0, 0, 0, 0);
        }
        __syncthreads();
        for (int p = tid; p < N4; p += NT) {
            uint4 k = keys4[p];
            atomicAdd(&s_hist[k.x >> 21], 1u);
            atomicAdd(&s_hist[k.y >> 21], 1u);
            atomicAdd(&s_hist[k.z >> 21], 1u);
            atomicAdd(&s_hist[k.w >> 21], 1u);
        }
        __syncthreads();
        {
            uint32_t cs = 0;
#pragma unroll
            for (int i = 0; i < 8; i++) cs += s_hist[tid * 8 + i];
            s_csum[tid] = cs;
        }
        __syncthreads();
        if (wid == 0) warp_select(s_hist, s_csum, KPRE, 0, s_sel);
        __syncthreads();
        uint32_t bbe = s_sel[0], n_above = s_sel[1];
        uint32_t Te = bbe << 21;
        if (tid == 0) s_cnt = 0;
        __syncthreads();
#define TRYPUSH(kk, pp, TH) \
        if ((kk) >= (TH)) { \
            uint32_t pos = atomicAdd(&s_cnt, 1u); \
            if (pos < CAP) s_cand[pos] = ((u64)(kk) << 32) | (uint32_t)(~(uint32_t)(pp)); }
        for (int p = tid; p < N4; p += NT) {
            uint4 k = keys4[p];
            int p0 = 4 * p;
            TRYPUSH(k.x, p0,     Te);
            TRYPUSH(k.y, p0 + 1, Te);
            TRYPUSH(k.z, p0 + 2, Te);
            TRYPUSH(k.w, p0 + 3, Te);
        }
        __syncthreads();
        M = s_cnt;
        if (M > CAP) {   // boundary bin too fat: refine globally to 21 bits
            for (int i = tid; i < 2048; i += NT) s_hist[i] = 0;
            __syncthreads();
            for (int p = tid; p < PNUM; p += NT) {
                uint32_t k = keys[p];
                if ((k >> 21) == bbe) atomicAdd(&s_hist[(k >> 10) & 0x7FFu], 1u);
            }
            __syncthreads();
            {
                uint32_t cs = 0;
#pragma unroll
                for (int i = 0; i < 8; i++) cs += s_hist[tid * 8 + i];
                s_csum[tid] = cs;
            }
            __syncthreads();
            if (wid == 0) warp_select(s_hist, s_csum, KPRE, n_above, s_sel);
            __syncthreads();
            uint32_t pref21 = (bbe << 11) | s_sel[0];
            if (tid == 0) s_cnt = 0;
            __syncthreads();
            for (int p = tid; p < PNUM; p += NT) {
                uint32_t k = keys[p];
                if ((k >> 10) >= pref21) {
                    uint32_t pos = atomicAdd(&s_cnt, 1u);
                    if (pos < CAP) s_cand[pos] = ((u64)k << 32) | (uint32_t)(~(uint32_t)p);
                }
            }
            __syncthreads();
            M = s_cnt;
            if (M > CAP) M = CAP;
        }
#undef TRYPUSH
    }

    // ============ in-shared refine, 4 levels x 8-bit digits -> exact F ============
    uint32_t pref = 0, n0 = 0;
#pragma unroll
    for (int lev = 0; lev < 4; lev++) {
        const int sh = 24 - lev * 8;
        if (tid < 256) s_hist[tid] = 0;
        __syncthreads();
        for (uint32_t i = tid; i < M; i += NT) {
            uint32_t k = (uint32_t)(s_cand[i] >> 32);
            bool match = (lev == 0) || ((k >> (sh + 8)) == pref);
            if (match) atomicAdd(&s_hist[(k >> sh) & 255u], 1u);
        }
        __syncthreads();
        if (wid == 0) warp_select256(s_hist, KPRE, n0, s_sel);
        __syncthreads();
        pref = (pref << 8) | s_sel[0];
        n0 = s_sel[1];
        __syncthreads();
    }
    const uint32_t F = pref;

    // ================= compact qualifying (key >= F) =================
    if (tid == 0) s_cnt = 0;
    __syncthreads();
    for (uint32_t i = tid; i < M; i += NT) {
        u64 c = s_cand[i];
        if ((uint32_t)(c >> 32) >= F) {
            uint32_t pos = atomicAdd(&s_cnt, 1u);
            if (pos < QCAP) s_h64[pos] = c;
        }
    }
    __syncthreads();
    uint32_t M2 = s_cnt; if (M2 > QCAP) M2 = QCAP;

    // ================= sort: bitonic-256 (generic) or rank-sort (ties) =================
    if (M2 == KPRE) {
        u64 mine = s_h64[tid];
        __syncthreads();
#pragma unroll
        for (uint32_t k = 2; k <= 256; k <<= 1) {
            for (uint32_t j = k >> 1; j >= 1; j >>= 1) {
                u64 other;
                if (j >= 32) {
                    s_key[tid] = mine;
                    __syncthreads();
                    other = s_key[tid ^ j];
                    __syncthreads();
                } else {
                    other = __shfl_xor_sync(0xFFFFFFFFu, mine, j);
                }
                bool lower   = (tid & j) == 0;
                bool dirDesc = (tid & k) == 0;
                bool takeMax = (lower == dirDesc);
                u64 mx = mine > other ? mine : other;
                u64 mn = mine > other ? other : mine;
                mine = takeMax ? mx : mn;
            }
        }
        s_key[tid] = mine;
    } else {
        for (uint32_t i = tid; i < M2; i += NT) {
            u64 mine = s_h64[i];
            uint32_t rank = 0;
            for (uint32_t j = 0; j < M2; j++) rank += (s_h64[j] > mine);
            if (rank < KPRE) s_key[rank] = mine;
        }
    }
    __syncthreads();

    // ======== extract top-256: decode box on demand (exact prep arithmetic) ========
    u64 key = s_key[tid];
    uint32_t idx = ~(uint32_t)key;
    float scv = unmono((uint32_t)(key >> 32));
    float4 bj;
    {
        float4 l  = __ldg((const float4*)loc + (size_t)b * PNUM + idx);
        float4 pr = __ldg((const float4*)prior + idx);
        float cx = pr.x + (l.x * 0.1f) * pr.z;
        float cy = pr.y + (l.y * 0.1f) * pr.w;
        float w  = pr.z * expf(l.z * 0.2f);
        float h  = pr.w * expf(l.w * 0.2f);
        float x1 = cx - w * 0.5f;
        float y1 = cy - h * 0.5f;
        bj = make_float4(x1, y1, x1 + w, y1 + h);
    }
    float aj = fmaxf(bj.z - bj.x, 0.f) * fmaxf(bj.w - bj.y, 0.f);
    s_box[tid]  = bj;
    s_area[tid] = aj;
    {
        bool valid = scv > 0.01f;
        uint32_t bal = __ballot_sync(0xFFFFFFFFu, valid);
        if (lane == 0) s_keep[wid] = bal;
    }
    if (tid < 8) s_rowmask[tid] = 0;
    float* op = out + (size_t)pair * (TOPK * 5);
    {   // float4 zeroing (TOPK*5*4 bytes = 4000, 16B-aligned)
        float4* op4 = (float4*)op;
        if (tid < TOPK * 5 / 4) op4[tid] = make_float4(0.f, 0.f, 0.f, 0.f);
    }
    uint32_t* s_supp = (uint32_t*)s_h64;
    __syncthreads();

    // ===== suppression bitmatrix: balanced schedule, FFMA-band IoU =====
#pragma unroll 1
    for (int g = 0; g < 8; g++) {
        const int    colg = g * 32 + lane;
        const float4 bg   = s_box[colg];
        const float  ag   = s_area[colg];
        const float  chi  = __fmul_rn(0.310395f, ag);
        const float  clo  = __fmul_rn(0.310295f, ag);
        const int    gbase = g * 32;
        // main rows: i < 32g -> colg > i always (no lane test), 4-wide unrolled
#pragma unroll 1
        for (int t = 0; t < g; t++) {
#pragma unroll
            for (int u = 0; u < 4; u++) {
                const int i = wid + t * 32 + u * 8;
                float4 bi = s_box[i];
                float wx = fmaxf(fminf(bi.z, bg.z) - fmaxf(bi.x, bg.x), 0.f);
                float wy = fmaxf(fminf(bi.w, bg.w) - fmaxf(bi.y, bg.y), 0.f);
                float inter = __fmul_rn(wx, wy);
                float ai = s_area[i];
                bool sup = inter > __fmaf_rn(0.310395f, ai, chi);
                if (!sup && inter >= __fmaf_rn(0.310295f, ai, clo)) {
                    float s  = __fadd_rn(ai, ag);
                    float ut = fmaxf(__fadd_rn(s, -inter), 1e-9f);
                    sup = (inter / ut) > 0.45f;           // exact IEEE path (rare)
                }
                uint32_t bal = __ballot_sync(0xFFFFFFFFu, sup);
                if (lane == 0) {
                    s_supp[i * 8 + g] = bal;
                    if (bal) atomicOr(&s_rowmask[i >> 5], 1u << (i & 31));
                }
            }
        }
        // diagonal rows: i in [32g, 32g+32) -> lane test needed
#pragma unroll
        for (int t = 0; t < 4; t++) {
            const int i = gbase + wid + t * 8;
            float4 bi = s_box[i];
            float wx = fmaxf(fminf(bi.z, bg.z) - fmaxf(bi.x, bg.x), 0.f);
            float wy = fmaxf(fminf(bi.w, bg.w) - fmaxf(bi.y, bg.y), 0.f);
            float inter = __fmul_rn(wx, wy);
            float ai = s_area[i];
            bool gt  = colg > i;
            bool sup = gt && (inter > __fmaf_rn(0.310395f, ai, chi));
            if (gt && !sup && inter >= __fmaf_rn(0.310295f, ai, clo)) {
                float s  = __fadd_rn(ai, ag);
                float ut = fmaxf(__fadd_rn(s, -inter), 1e-9f);
                sup = (inter / ut) > 0.45f;
            }
            uint32_t bal = __ballot_sync(0xFFFFFFFFu, sup);
            if (lane == 0) {
                s_supp[i * 8 + g] = bal;
                if (bal) atomicOr(&s_rowmask[i >> 5], 1u << (i & 31));
            }
        }
    }
    __syncthreads();

    // ====== sparse greedy scan on warp 0 (only rows that suppress someone) ======
    if (wid == 0) {
        uint32_t kw = (lane < 8) ? s_keep[lane] : 0u;
        for (int w8 = 0; w8 < 8; w8++) {
            uint32_t rm = s_rowmask[w8];
            while (rm) {
                int bit = __ffs(rm) - 1; rm &= rm - 1;
                int i = w8 * 32 + bit;
                uint32_t w = __shfl_sync(0xFFFFFFFFu, kw, w8);
                uint32_t cur = (lane < 8 && lane >= w8) ? s_supp[i * 8 + lane] : 0u;
                if ((w >> bit) & 1u)
                    kw &= ~cur;
            }
        }
        if (lane < 8) s_keep[lane] = kw;
    }
    __syncthreads();

    // ================= compaction + output =================
    if (tid == 0) {
        uint32_t a = 0;
#pragma unroll
        for (int w2 = 0; w2 < 8; w2++) { s_wpre[w2] = a; a += __popc(s_keep[w2]); }
        g_cnt[pair] = 0;   // reset speculative counter for the next launch/replay
    }
    __syncthreads();

    uint32_t kwm = s_keep[wid];
    if ((kwm >> lane) & 1u) {
        uint32_t rank = s_wpre[wid] + __popc(kwm & ((1u << lane) - 1u));
        if (rank < TOPK) {
            float* r = op + (size_t)rank * 5;
            r[0] = scv;
            r[1] = bj.x; r[2] = bj.y; r[3] = bj.z; r[4] = bj.w;
        }
    }
}

// ------------------------------------------------------------------
extern "C" void kernel_launch(void* const* d_in, const int* in_sizes, int n_in,
                              void* d_out, int out_size) {
    const float* loc   = (const float*)d_in[0];
    const float* conf  = (const float*)d_in[1];
    const float* prior = (const float*)d_in[2];
    float* out = (float*)d_out;

    int total = BNUM * PNUM;
    prep_kernel<<<(total + 255) / 256, 256>>>(conf);
    topk_nms_kernel<<<NPAIR, NT>>>(out, loc, prior);
}

// round 14
// speedup vs baseline: 1.6289x; 1.6289x over previous
#include <cuda_runtime.h>
#include <stdint.h>

#define BNUM 32
#define PNUM 8732
#define CFG  20
#define NPAIR (BNUM*CFG)
#define KPRE 256
#define TOPK 200
#define CAP  2048
#define QCAP 1024
#define NT   256

typedef unsigned long long u64;

// ------------------------------------------------------------------
__device__ uint32_t g_keys[(size_t)NPAIR * PNUM];   // mono(prob) per [b][c][p] (fallback only)
__device__ u64      g_list[(size_t)NPAIR * CAP];    // speculative candidate lists
__device__ uint32_t g_cnt[NPAIR];                   // list counters (zeroed by topk epilogue)

__device__ __forceinline__ uint32_t mono(float f) {
    uint32_t u = __float_as_uint(f);
    return (u & 0x80000000u) ? ~u : (u | 0x80000000u);
}
__device__ __forceinline__ float unmono(uint32_t k) {
    uint32_t u = (k & 0x80000000u) ? (k ^ 0x80000000u) : ~k;
    return __uint_as_float(u);
}

// fixed speculative threshold: prob 0.10 (P(key>=T) ~ 10% per pair here;
// any pair outside [KPRE, CAP] takes the exact global fallback in topk)
#define T_FIXED 0xBDCCCCCDu   // mono(0.10f)

// ------------------------------------------------------------------
// kernel 1: softmax (exact jax.nn.softmax order) -> mono keys
//           + warp-aggregated speculative push (blockIdx.y = b, so the
//           destination list is warp-uniform per class)
// ------------------------------------------------------------------
__global__ __launch_bounds__(256) void prep_kernel(const float* __restrict__ conf) {
    const int p  = blockIdx.x * 256 + threadIdx.x;
    const int b  = blockIdx.y;
    const int lane = threadIdx.x & 31;
    const bool in = p < PNUM;
    const int g  = b * PNUM + p;

    float e[21];
    float s = 1.f;   // placeholder; overwritten when in
    if (in) {
        const float* cp = conf + (size_t)g * 21;
        float x[21];
#pragma unroll
        for (int c = 0; c < 21; c++) x[c] = cp[c];
        float m = x[0];
#pragma unroll
        for (int c = 1; c < 21; c++) m = fmaxf(m, x[c]);
        s = 0.f;
#pragma unroll
        for (int c = 0; c < 21; c++) { e[c] = expf(x[c] - m); s += e[c]; }
    }

#pragma unroll
    for (int c = 1; c < 21; c++) {
        const int pairIdx = b * CFG + (c - 1);
        uint32_t k = 0;
        if (in) {
            k = mono(e[c] / s);
            g_keys[(size_t)pairIdx * PNUM + p] = k;
        }
        // warp-aggregated push (uniform control flow; pairIdx warp-uniform)
        bool q = in && (k >= T_FIXED);
        uint32_t bal = __ballot_sync(0xFFFFFFFFu, q);
        if (bal) {
            int ldr = __ffs(bal) - 1;
            uint32_t base = 0;
            if (lane == ldr) base = atomicAdd(&g_cnt[pairIdx], (uint32_t)__popc(bal));
            base = __shfl_sync(0xFFFFFFFFu, base, ldr);
            if (q) {
                uint32_t pos = base + __popc(bal & ((1u << lane) - 1u));
                if (pos < CAP)
                    g_list[(size_t)pairIdx * CAP + pos] =
                        ((u64)k << 32) | (uint32_t)(~(uint32_t)p);
            }
        }
    }
}

// ------------------------------------------------------------------
// warp 0 helpers (called by all 32 lanes of warp 0)
// ------------------------------------------------------------------
__device__ __forceinline__ void warp_select(const uint32_t* s_hist,
                                            const uint32_t* s_csum,
                                            uint32_t target, uint32_t n0,
                                            volatile uint32_t* s_sel) {
    const int l = threadIdx.x;
    uint32_t v[8]; uint32_t tot = 0;
#pragma unroll
    for (int m = 0; m < 8; m++) { v[m] = s_csum[l * 8 + m]; tot += v[m]; }
    uint32_t incl = tot;
#pragma unroll
    for (int o = 1; o < 32; o <<= 1) {
        uint32_t t = __shfl_down_sync(0xFFFFFFFFu, incl, o);
        if (l + o < 32) incl += t;
    }
    uint32_t above = incl - tot;
    if ((above + n0 < target) && (incl + n0 >= target)) {
        uint32_t acc = above + n0;
        int mm = 0;
        for (int m = 7; m >= 0; m--) {
            if (acc + v[m] >= target) { mm = m; break; }
            acc += v[m];
        }
        int chunk = l * 8 + mm;
        int bb = chunk * 8;
        for (int bi = chunk * 8 + 7; bi >= chunk * 8; bi--) {
            uint32_t h = s_hist[bi];
            if (acc + h >= target) { bb = bi; break; }
            acc += h;
        }
        s_sel[0] = (uint32_t)bb; s_sel[1] = acc;
    }
}

__device__ __forceinline__ void warp_select256(const uint32_t* s_hist,
                                               uint32_t target, uint32_t n0,
                                               volatile uint32_t* s_sel) {
    const int l = threadIdx.x;
    uint32_t v[8]; uint32_t tot = 0;
#pragma unroll
    for (int m = 0; m < 8; m++) { v[m] = s_hist[l * 8 + m]; tot += v[m]; }
    uint32_t incl = tot;
#pragma unroll
    for (int o = 1; o < 32; o <<= 1) {
        uint32_t t = __shfl_down_sync(0xFFFFFFFFu, incl, o);
        if (l + o < 32) incl += t;
    }
    uint32_t above = incl - tot;
    if ((above + n0 < target) && (incl + n0 >= target)) {
        uint32_t acc = above + n0;
        int bb = l * 8;
        for (int m = 7; m >= 0; m--) {
            if (acc + v[m] >= target) { bb = l * 8 + m; break; }
            acc += v[m];
        }
        s_sel[0] = (uint32_t)bb; s_sel[1] = acc;
    }
}

// ------------------------------------------------------------------
// kernel 2: per (b,c) pair
// ------------------------------------------------------------------
__global__ __launch_bounds__(NT) void topk_nms_kernel(float* __restrict__ out,
                                                      const float* __restrict__ loc,
                                                      const float* __restrict__ prior) {
    __shared__ u64      s_h64[1024];     // hist(2048 u32) / compacted / supp matrix
    __shared__ uint32_t s_csum[256];
    __shared__ u64      s_cand[CAP];
    __shared__ u64      s_key[KPRE];
    __shared__ float4   s_box[KPRE];
    __shared__ float    s_area[KPRE];
    __shared__ uint32_t s_keep[8];
    __shared__ uint32_t s_wpre[8];
    __shared__ uint32_t s_rowmask[8];
    __shared__ uint32_t s_sel[2];
    __shared__ uint32_t s_cnt;
    uint32_t* s_hist = (uint32_t*)s_h64;

    const int pair = blockIdx.x;
    const int b    = pair / CFG;
    const int tid  = threadIdx.x;
    const int wid  = tid >> 5, lane = tid & 31;
    const uint32_t* __restrict__ keys = g_keys + (size_t)pair * PNUM;
    const uint4* __restrict__ keys4 = (const uint4*)keys;
    const int N4 = PNUM / 4;  // 2183

    // ============ candidate set: speculative list from prep (fast path) ============
    uint32_t M = g_cnt[pair];
    if (M >= KPRE && M <= CAP) {
        const u64* __restrict__ lst = g_list + (size_t)pair * CAP;
        for (uint32_t i = tid; i < M; i += NT) s_cand[i] = lst[i];
        __syncthreads();
    } else {
        // ============ exact global select fallback (rare / adversarial data) ============
        {
            uint4* hz = (uint4*)s_hist;
            hz[tid] = make_uint4(0, 0, 0, 0);
            hz[tid + 256] = make_uint4(0, 0, 0, 0);
        }
        __syncthreads();
        for (int p = tid; p < N4; p += NT) {
            uint4 k = keys4[p];
            atomicAdd(&s_hist[k.x >> 21], 1u);
            atomicAdd(&s_hist[k.y >> 21], 1u);
            atomicAdd(&s_hist[k.z >> 21], 1u);
            atomicAdd(&s_hist[k.w >> 21], 1u);
        }
        __syncthreads();
        {
            uint32_t cs = 0;
#pragma unroll
            for (int i = 0; i < 8; i++) cs += s_hist[tid * 8 + i];
            s_csum[tid] = cs;
        }
        __syncthreads();
        if (wid == 0) warp_select(s_hist, s_csum, KPRE, 0, s_sel);
        __syncthreads();
        uint32_t bbe = s_sel[0], n_above = s_sel[1];
        uint32_t Te = bbe << 21;
        if (tid == 0) s_cnt = 0;
        __syncthreads();
#define TRYPUSH(kk, pp, TH) \
        if ((kk) >= (TH)) { \
            uint32_t pos = atomicAdd(&s_cnt, 1u); \
            if (pos < CAP) s_cand[pos] = ((u64)(kk) << 32) | (uint32_t)(~(uint32_t)(pp)); }
        for (int p = tid; p < N4; p += NT) {
            uint4 k = keys4[p];
            int p0 = 4 * p;
            TRYPUSH(k.x, p0,     Te);
            TRYPUSH(k.y, p0 + 1, Te);
            TRYPUSH(k.z, p0 + 2, Te);
            TRYPUSH(k.w, p0 + 3, Te);
        }
        __syncthreads();
        M = s_cnt;
        if (M > CAP) {   // boundary bin too fat: refine globally to 21 bits
            for (int i = tid; i < 2048; i += NT) s_hist[i] = 0;
            __syncthreads();
            for (int p = tid; p < PNUM; p += NT) {
                uint32_t k = keys[p];
                if ((k >> 21) == bbe) atomicAdd(&s_hist[(k >> 10) & 0x7FFu], 1u);
            }
            __syncthreads();
            {
                uint32_t cs = 0;
#pragma unroll
                for (int i = 0; i < 8; i++) cs += s_hist[tid * 8 + i];
                s_csum[tid] = cs;
            }
            __syncthreads();
            if (wid == 0) warp_select(s_hist, s_csum, KPRE, n_above, s_sel);
            __syncthreads();
            uint32_t pref21 = (bbe << 11) | s_sel[0];
            if (tid == 0) s_cnt = 0;
            __syncthreads();
            for (int p = tid; p < PNUM; p += NT) {
                uint32_t k = keys[p];
                if ((k >> 10) >= pref21) {
                    uint32_t pos = atomicAdd(&s_cnt, 1u);
                    if (pos < CAP) s_cand[pos] = ((u64)k << 32) | (uint32_t)(~(uint32_t)p);
                }
            }
            __syncthreads();
            M = s_cnt;
            if (M > CAP) M = CAP;
        }
#undef TRYPUSH
    }

    // ============ in-shared refine, 4 levels x 8-bit digits -> exact F ============
    uint32_t pref = 0, n0 = 0;
#pragma unroll
    for (int lev = 0; lev < 4; lev++) {
        const int sh = 24 - lev * 8;
        if (tid < 256) s_hist[tid] = 0;
        __syncthreads();
        for (uint32_t i = tid; i < M; i += NT) {
            uint32_t k = (uint32_t)(s_cand[i] >> 32);
            bool match = (lev == 0) || ((k >> (sh + 8)) == pref);
            if (match) atomicAdd(&s_hist[(k >> sh) & 255u], 1u);
        }
        __syncthreads();
        if (wid == 0) warp_select256(s_hist, KPRE, n0, s_sel);
        __syncthreads();
        pref = (pref << 8) | s_sel[0];
        n0 = s_sel[1];
        __syncthreads();
    }
    const uint32_t F = pref;

    // ================= compact qualifying (key >= F) =================
    if (tid == 0) s_cnt = 0;
    __syncthreads();
    for (uint32_t i = tid; i < M; i += NT) {
        u64 c = s_cand[i];
        if ((uint32_t)(c >> 32) >= F) {
            uint32_t pos = atomicAdd(&s_cnt, 1u);
            if (pos < QCAP) s_h64[pos] = c;
        }
    }
    __syncthreads();
    uint32_t M2 = s_cnt; if (M2 > QCAP) M2 = QCAP;

    // ================= sort: bitonic-256 (generic) or rank-sort (ties) =================
    if (M2 == KPRE) {
        u64 mine = s_h64[tid];
        __syncthreads();
#pragma unroll
        for (uint32_t k = 2; k <= 256; k <<= 1) {
            for (uint32_t j = k >> 1; j >= 1; j >>= 1) {
                u64 other;
                if (j >= 32) {
                    s_key[tid] = mine;
                    __syncthreads();
                    other = s_key[tid ^ j];
                    __syncthreads();
                } else {
                    other = __shfl_xor_sync(0xFFFFFFFFu, mine, j);
                }
                bool lower   = (tid & j) == 0;
                bool dirDesc = (tid & k) == 0;
                bool takeMax = (lower == dirDesc);
                u64 mx = mine > other ? mine : other;
                u64 mn = mine > other ? other : mine;
                mine = takeMax ? mx : mn;
            }
        }
        s_key[tid] = mine;
    } else {
        for (uint32_t i = tid; i < M2; i += NT) {
            u64 mine = s_h64[i];
            uint32_t rank = 0;
            for (uint32_t j = 0; j < M2; j++) rank += (s_h64[j] > mine);
            if (rank < KPRE) s_key[rank] = mine;
        }
    }
    __syncthreads();

    // ======== extract top-256: decode box on demand (exact prep arithmetic) ========
    u64 key = s_key[tid];
    uint32_t idx = ~(uint32_t)key;
    float scv = unmono((uint32_t)(key >> 32));
    float4 bj;
    {
        float4 l  = __ldg((const float4*)loc + (size_t)b * PNUM + idx);
        float4 pr = __ldg((const float4*)prior + idx);
        float cx = pr.x + (l.x * 0.1f) * pr.z;
        float cy = pr.y + (l.y * 0.1f) * pr.w;
        float w  = pr.z * expf(l.z * 0.2f);
        float h  = pr.w * expf(l.w * 0.2f);
        float x1 = cx - w * 0.5f;
        float y1 = cy - h * 0.5f;
        bj = make_float4(x1, y1, x1 + w, y1 + h);
    }
    float aj = fmaxf(bj.z - bj.x, 0.f) * fmaxf(bj.w - bj.y, 0.f);
    s_box[tid]  = bj;
    s_area[tid] = aj;
    {
        bool valid = scv > 0.01f;
        uint32_t bal = __ballot_sync(0xFFFFFFFFu, valid);
        if (lane == 0) s_keep[wid] = bal;
    }
    if (tid < 8) s_rowmask[tid] = 0;
    float* op = out + (size_t)pair * (TOPK * 5);
    {
        float4* op4 = (float4*)op;
        if (tid < TOPK * 5 / 4) op4[tid] = make_float4(0.f, 0.f, 0.f, 0.f);
    }
    uint32_t* s_supp = (uint32_t*)s_h64;
    __syncthreads();

    // ===== suppression bitmatrix: balanced schedule, FFMA-band IoU =====
#pragma unroll 1
    for (int g = 0; g < 8; g++) {
        const int    colg = g * 32 + lane;
        const float4 bg   = s_box[colg];
        const float  ag   = s_area[colg];
        const float  chi  = __fmul_rn(0.310395f, ag);
        const float  clo  = __fmul_rn(0.310295f, ag);
        const int    gbase = g * 32;
#pragma unroll 1
        for (int t = 0; t < g; t++) {
#pragma unroll
            for (int u = 0; u < 4; u++) {
                const int i = wid + t * 32 + u * 8;
                float4 bi = s_box[i];
                float wx = fmaxf(fminf(bi.z, bg.z) - fmaxf(bi.x, bg.x), 0.f);
                float wy = fmaxf(fminf(bi.w, bg.w) - fmaxf(bi.y, bg.y), 0.f);
                float inter = __fmul_rn(wx, wy);
                float ai = s_area[i];
                bool sup = inter > __fmaf_rn(0.310395f, ai, chi);
                if (!sup && inter >= __fmaf_rn(0.310295f, ai, clo)) {
                    float s  = __fadd_rn(ai, ag);
                    float ut = fmaxf(__fadd_rn(s, -inter), 1e-9f);
                    sup = (inter / ut) > 0.45f;           // exact IEEE path (rare)
                }
                uint32_t bal = __ballot_sync(0xFFFFFFFFu, sup);
                if (lane == 0) {
                    s_supp[i * 8 + g] = bal;
                    if (bal) atomicOr(&s_rowmask[i >> 5], 1u << (i & 31));
                }
            }
        }
#pragma unroll
        for (int t = 0; t < 4; t++) {
            const int i = gbase + wid + t * 8;
            float4 bi = s_box[i];
            float wx = fmaxf(fminf(bi.z, bg.z) - fmaxf(bi.x, bg.x), 0.f);
            float wy = fmaxf(fminf(bi.w, bg.w) - fmaxf(bi.y, bg.y), 0.f);
            float inter = __fmul_rn(wx, wy);
            float ai = s_area[i];
            bool gt  = colg > i;
            bool sup = gt && (inter > __fmaf_rn(0.310395f, ai, chi));
            if (gt && !sup && inter >= __fmaf_rn(0.310295f, ai, clo)) {
                float s  = __fadd_rn(ai, ag);
                float ut = fmaxf(__fadd_rn(s, -inter), 1e-9f);
                sup = (inter / ut) > 0.45f;
            }
            uint32_t bal = __ballot_sync(0xFFFFFFFFu, sup);
            if (lane == 0) {
                s_supp[i * 8 + g] = bal;
                if (bal) atomicOr(&s_rowmask[i >> 5], 1u << (i & 31));
            }
        }
    }
    __syncthreads();

    // ====== sparse greedy scan on warp 0 (only rows that suppress someone) ======
    if (wid == 0) {
        uint32_t kw = (lane < 8) ? s_keep[lane] : 0u;
        for (int w8 = 0; w8 < 8; w8++) {
            uint32_t rm = s_rowmask[w8];
            while (rm) {
                int bit = __ffs(rm) - 1; rm &= rm - 1;
                int i = w8 * 32 + bit;
                uint32_t w = __shfl_sync(0xFFFFFFFFu, kw, w8);
                uint32_t cur = (lane < 8 && lane >= w8) ? s_supp[i * 8 + lane] : 0u;
                if ((w >> bit) & 1u)
                    kw &= ~cur;
            }
        }
        if (lane < 8) s_keep[lane] = kw;
    }
    __syncthreads();

    // ================= compaction + output =================
    if (tid == 0) {
        uint32_t a = 0;
#pragma unroll
        for (int w2 = 0; w2 < 8; w2++) { s_wpre[w2] = a; a += __popc(s_keep[w2]); }
        g_cnt[pair] = 0;   // reset speculative counter for the next launch/replay
    }
    __syncthreads();

    uint32_t kwm = s_keep[wid];
    if ((kwm >> lane) & 1u) {
        uint32_t rank = s_wpre[wid] + __popc(kwm & ((1u << lane) - 1u));
        if (rank < TOPK) {
            float* r = op + (size_t)rank * 5;
            r[0] = scv;
            r[1] = bj.x; r[2] = bj.y; r[3] = bj.z; r[4] = bj.w;
        }
    }
}

// ------------------------------------------------------------------
extern "C" void kernel_launch(void* const* d_in, const int* in_sizes, int n_in,
                              void* d_out, int out_size) {
    const float* loc   = (const float*)d_in[0];
    const float* conf  = (const float*)d_in[1];
    const float* prior = (const float*)d_in[2];
    float* out = (float*)d_out;

    dim3 pgrid((PNUM + 255) / 256, BNUM);
    prep_kernel<<<pgrid, 256>>>(conf);
    topk_nms_kernel<<<NPAIR, NT>>>(out, loc, prior);
}

// round 15
// speedup vs baseline: 1.9358x; 1.1884x over previous
#include <cuda_runtime.h>
#include <stdint.h>

#define BNUM 32
#define PNUM 8732
#define CFG  20
#define NPAIR (BNUM*CFG)
#define KPRE 256
#define TOPK 200
#define CAP  2048
#define QCAP 1024
#define NT   256

typedef unsigned long long u64;

// ------------------------------------------------------------------
__device__ uint32_t g_keys[(size_t)NPAIR * PNUM];   // mono(prob) per [b][c][p] (fallback only)
__device__ u64      g_list[(size_t)NPAIR * CAP];    // speculative candidate lists
__device__ uint32_t g_cnt[NPAIR];                   // list counters (zeroed by topk epilogue)

__device__ __forceinline__ uint32_t mono(float f) {
    uint32_t u = __float_as_uint(f);
    return (u & 0x80000000u) ? ~u : (u | 0x80000000u);
}
__device__ __forceinline__ float unmono(uint32_t k) {
    uint32_t u = (k & 0x80000000u) ? (k ^ 0x80000000u) : ~k;
    return __uint_as_float(u);
}

// fixed speculative threshold: prob 0.10 (P(key>=T) ~ 10% per pair here;
// any pair outside [KPRE, CAP] takes the exact global fallback in topk)
#define T_FIXED 0xBDCCCCCDu   // mono(0.10f)

// ------------------------------------------------------------------
// kernel 1: softmax (exact jax.nn.softmax order) -> mono keys
//   + speculative push with ONE parallel atomic round per warp:
//     lanes 0..19 reserve space for classes 1..20 concurrently.
// ------------------------------------------------------------------
__global__ __launch_bounds__(256) void prep_kernel(const float* __restrict__ conf) {
    const int p    = blockIdx.x * 256 + threadIdx.x;
    const int b    = blockIdx.y;
    const int lane = threadIdx.x & 31;
    const bool in  = p < PNUM;
    const int g    = b * PNUM + p;

    // --- softmax (guarded; no early return so warp stays converged) ---
    float e[21];
    float s = 1.f;
    if (in) {
        const float* cp = conf + (size_t)g * 21;
        float x[21];
#pragma unroll
        for (int c = 0; c < 21; c++) x[c] = cp[c];
        float m = x[0];
#pragma unroll
        for (int c = 1; c < 21; c++) m = fmaxf(m, x[c]);
        s = 0.f;
#pragma unroll
        for (int c = 0; c < 21; c++) { e[c] = expf(x[c] - m); s += e[c]; }
    }

    // --- phase 1: keys, coalesced key-store, ballots (all uniform flow) ---
    uint32_t kk[CFG];
    uint32_t bal[CFG];
    bool     q[CFG];
    uint32_t mybal = 0;
#pragma unroll
    for (int c = 0; c < CFG; c++) {
        kk[c] = 0;
        if (in) {
            kk[c] = mono(e[c + 1] / s);
            g_keys[(size_t)(b * CFG + c) * PNUM + p] = kk[c];
        }
        q[c] = in && (kk[c] >= T_FIXED);
        bal[c] = __ballot_sync(0xFFFFFFFFu, q[c]);
        if (lane == c) mybal = bal[c];   // lane c latches class c's ballot
    }

    // --- phase 2: ONE atomic instruction, lanes 0..19 active, 20 distinct counters ---
    uint32_t base = 0;
    if (lane < CFG && mybal)
        base = atomicAdd(&g_cnt[b * CFG + lane], (uint32_t)__popc(mybal));

    // --- phase 3: scatter (bases broadcast via shfl; uniform flow) ---
    const uint32_t ltmask = (1u << lane) - 1u;
#pragma unroll
    for (int c = 0; c < CFG; c++) {
        uint32_t bc = __shfl_sync(0xFFFFFFFFu, base, c);
        if (q[c]) {
            uint32_t pos = bc + __popc(bal[c] & ltmask);
            if (pos < CAP)
                g_list[(size_t)(b * CFG + c) * CAP + pos] =
                    ((u64)kk[c] << 32) | (uint32_t)(~(uint32_t)p);
        }
    }
}

// ------------------------------------------------------------------
// warp 0 helpers (called by all 32 lanes of warp 0)
// ------------------------------------------------------------------
__device__ __forceinline__ void warp_select(const uint32_t* s_hist,
                                            const uint32_t* s_csum,
                                            uint32_t target, uint32_t n0,
                                            volatile uint32_t* s_sel) {
    const int l = threadIdx.x;
    uint32_t v[8]; uint32_t tot = 0;
#pragma unroll
    for (int m = 0; m < 8; m++) { v[m] = s_csum[l * 8 + m]; tot += v[m]; }
    uint32_t incl = tot;
#pragma unroll
    for (int o = 1; o < 32; o <<= 1) {
        uint32_t t = __shfl_down_sync(0xFFFFFFFFu, incl, o);
        if (l + o < 32) incl += t;
    }
    uint32_t above = incl - tot;
    if ((above + n0 < target) && (incl + n0 >= target)) {
        uint32_t acc = above + n0;
        int mm = 0;
        for (int m = 7; m >= 0; m--) {
            if (acc + v[m] >= target) { mm = m; break; }
            acc += v[m];
        }
        int chunk = l * 8 + mm;
        int bb = chunk * 8;
        for (int bi = chunk * 8 + 7; bi >= chunk * 8; bi--) {
            uint32_t h = s_hist[bi];
            if (acc + h >= target) { bb = bi; break; }
            acc += h;
        }
        s_sel[0] = (uint32_t)bb; s_sel[1] = acc;
    }
}

__device__ __forceinline__ void warp_select256(const uint32_t* s_hist,
                                               uint32_t target, uint32_t n0,
                                               volatile uint32_t* s_sel) {
    const int l = threadIdx.x;
    uint32_t v[8]; uint32_t tot = 0;
#pragma unroll
    for (int m = 0; m < 8; m++) { v[m] = s_hist[l * 8 + m]; tot += v[m]; }
    uint32_t incl = tot;
#pragma unroll
    for (int o = 1; o < 32; o <<= 1) {
        uint32_t t = __shfl_down_sync(0xFFFFFFFFu, incl, o);
        if (l + o < 32) incl += t;
    }
    uint32_t above = incl - tot;
    if ((above + n0 < target) && (incl + n0 >= target)) {
        uint32_t acc = above + n0;
        int bb = l * 8;
        for (int m = 7; m >= 0; m--) {
            if (acc + v[m] >= target) { bb = l * 8 + m; break; }
            acc += v[m];
        }
        s_sel[0] = (uint32_t)bb; s_sel[1] = acc;
    }
}

// ------------------------------------------------------------------
// kernel 2: per (b,c) pair
// ------------------------------------------------------------------
__global__ __launch_bounds__(NT) void topk_nms_kernel(float* __restrict__ out,
                                                      const float* __restrict__ loc,
                                                      const float* __restrict__ prior) {
    __shared__ u64      s_h64[1024];     // hist(2048 u32) / compacted / supp matrix
    __shared__ uint32_t s_csum[256];
    __shared__ u64      s_cand[CAP];
    __shared__ u64      s_key[KPRE];
    __shared__ float4   s_box[KPRE];
    __shared__ float    s_area[KPRE];
    __shared__ uint32_t s_keep[8];
    __shared__ uint32_t s_wpre[8];
    __shared__ uint32_t s_rowmask[8];
    __shared__ uint32_t s_sel[2];
    __shared__ uint32_t s_cnt;
    uint32_t* s_hist = (uint32_t*)s_h64;

    const int pair = blockIdx.x;
    const int b    = pair / CFG;
    const int tid  = threadIdx.x;
    const int wid  = tid >> 5, lane = tid & 31;
    const uint32_t* __restrict__ keys = g_keys + (size_t)pair * PNUM;
    const uint4* __restrict__ keys4 = (const uint4*)keys;
    const int N4 = PNUM / 4;  // 2183

    // ============ candidate set: speculative list from prep (fast path) ============
    uint32_t M = g_cnt[pair];
    if (M >= KPRE && M <= CAP) {
        const u64* __restrict__ lst = g_list + (size_t)pair * CAP;
        for (uint32_t i = tid; i < M; i += NT) s_cand[i] = lst[i];
        __syncthreads();
    } else {
        // ============ exact global select fallback (rare / adversarial data) ============
        {
            uint4* hz = (uint4*)s_hist;
            hz[tid] = make_uint4(0, 0, 0, 0);
            hz[tid + 256] = make_uint4(0, 0, 0, 0);
        }
        __syncthreads();
        for (int p = tid; p < N4; p += NT) {
            uint4 k = keys4[p];
            atomicAdd(&s_hist[k.x >> 21], 1u);
            atomicAdd(&s_hist[k.y >> 21], 1u);
            atomicAdd(&s_hist[k.z >> 21], 1u);
            atomicAdd(&s_hist[k.w >> 21], 1u);
        }
        __syncthreads();
        {
            uint32_t cs = 0;
#pragma unroll
            for (int i = 0; i < 8; i++) cs += s_hist[tid * 8 + i];
            s_csum[tid] = cs;
        }
        __syncthreads();
        if (wid == 0) warp_select(s_hist, s_csum, KPRE, 0, s_sel);
        __syncthreads();
        uint32_t bbe = s_sel[0], n_above = s_sel[1];
        uint32_t Te = bbe << 21;
        if (tid == 0) s_cnt = 0;
        __syncthreads();
#define TRYPUSH(kk, pp, TH) \
        if ((kk) >= (TH)) { \
            uint32_t pos = atomicAdd(&s_cnt, 1u); \
            if (pos < CAP) s_cand[pos] = ((u64)(kk) << 32) | (uint32_t)(~(uint32_t)(pp)); }
        for (int p = tid; p < N4; p += NT) {
            uint4 k = keys4[p];
            int p0 = 4 * p;
            TRYPUSH(k.x, p0,     Te);
            TRYPUSH(k.y, p0 + 1, Te);
            TRYPUSH(k.z, p0 + 2, Te);
            TRYPUSH(k.w, p0 + 3, Te);
        }
        __syncthreads();
        M = s_cnt;
        if (M > CAP) {   // boundary bin too fat: refine globally to 21 bits
            for (int i = tid; i < 2048; i += NT) s_hist[i] = 0;
            __syncthreads();
            for (int p = tid; p < PNUM; p += NT) {
                uint32_t k = keys[p];
                if ((k >> 21) == bbe) atomicAdd(&s_hist[(k >> 10) & 0x7FFu], 1u);
            }
            __syncthreads();
            {
                uint32_t cs = 0;
#pragma unroll
                for (int i = 0; i < 8; i++) cs += s_hist[tid * 8 + i];
                s_csum[tid] = cs;
            }
            __syncthreads();
            if (wid == 0) warp_select(s_hist, s_csum, KPRE, n_above, s_sel);
            __syncthreads();
            uint32_t pref21 = (bbe << 11) | s_sel[0];
            if (tid == 0) s_cnt = 0;
            __syncthreads();
            for (int p = tid; p < PNUM; p += NT) {
                uint32_t k = keys[p];
                if ((k >> 10) >= pref21) {
                    uint32_t pos = atomicAdd(&s_cnt, 1u);
                    if (pos < CAP) s_cand[pos] = ((u64)k << 32) | (uint32_t)(~(uint32_t)p);
                }
            }
            __syncthreads();
            M = s_cnt;
            if (M > CAP) M = CAP;
        }
#undef TRYPUSH
    }

    // ============ in-shared refine, 4 levels x 8-bit digits -> exact F ============
    uint32_t pref = 0, n0 = 0;
#pragma unroll
    for (int lev = 0; lev < 4; lev++) {
        const int sh = 24 - lev * 8;
        if (tid < 256) s_hist[tid] = 0;
        __syncthreads();
        for (uint32_t i = tid; i < M; i += NT) {
            uint32_t k = (uint32_t)(s_cand[i] >> 32);
            bool match = (lev == 0) || ((k >> (sh + 8)) == pref);
            if (match) atomicAdd(&s_hist[(k >> sh) & 255u], 1u);
        }
        __syncthreads();
        if (wid == 0) warp_select256(s_hist, KPRE, n0, s_sel);
        __syncthreads();
        pref = (pref << 8) | s_sel[0];
        n0 = s_sel[1];
        __syncthreads();
    }
    const uint32_t F = pref;

    // ================= compact qualifying (key >= F) =================
    if (tid == 0) s_cnt = 0;
    __syncthreads();
    for (uint32_t i = tid; i < M; i += NT) {
        u64 c = s_cand[i];
        if ((uint32_t)(c >> 32) >= F) {
            uint32_t pos = atomicAdd(&s_cnt, 1u);
            if (pos < QCAP) s_h64[pos] = c;
        }
    }
    __syncthreads();
    uint32_t M2 = s_cnt; if (M2 > QCAP) M2 = QCAP;

    // ================= sort: bitonic-256 (generic) or rank-sort (ties) =================
    if (M2 == KPRE) {
        u64 mine = s_h64[tid];
        __syncthreads();
#pragma unroll
        for (uint32_t k = 2; k <= 256; k <<= 1) {
            for (uint32_t j = k >> 1; j >= 1; j >>= 1) {
                u64 other;
                if (j >= 32) {
                    s_key[tid] = mine;
                    __syncthreads();
                    other = s_key[tid ^ j];
                    __syncthreads();
                } else {
                    other = __shfl_xor_sync(0xFFFFFFFFu, mine, j);
                }
                bool lower   = (tid & j) == 0;
                bool dirDesc = (tid & k) == 0;
                bool takeMax = (lower == dirDesc);
                u64 mx = mine > other ? mine : other;
                u64 mn = mine > other ? other : mine;
                mine = takeMax ? mx : mn;
            }
        }
        s_key[tid] = mine;
    } else {
        for (uint32_t i = tid; i < M2; i += NT) {
            u64 mine = s_h64[i];
            uint32_t rank = 0;
            for (uint32_t j = 0; j < M2; j++) rank += (s_h64[j] > mine);
            if (rank < KPRE) s_key[rank] = mine;
        }
    }
    __syncthreads();

    // ======== extract top-256: decode box on demand (exact prep arithmetic) ========
    u64 key = s_key[tid];
    uint32_t idx = ~(uint32_t)key;
    float scv = unmono((uint32_t)(key >> 32));
    float4 bj;
    {
        float4 l  = __ldg((const float4*)loc + (size_t)b * PNUM + idx);
        float4 pr = __ldg((const float4*)prior + idx);
        float cx = pr.x + (l.x * 0.1f) * pr.z;
        float cy = pr.y + (l.y * 0.1f) * pr.w;
        float w  = pr.z * expf(l.z * 0.2f);
        float h  = pr.w * expf(l.w * 0.2f);
        float x1 = cx - w * 0.5f;
        float y1 = cy - h * 0.5f;
        bj = make_float4(x1, y1, x1 + w, y1 + h);
    }
    float aj = fmaxf(bj.z - bj.x, 0.f) * fmaxf(bj.w - bj.y, 0.f);
    s_box[tid]  = bj;
    s_area[tid] = aj;
    {
        bool valid = scv > 0.01f;
        uint32_t bal = __ballot_sync(0xFFFFFFFFu, valid);
        if (lane == 0) s_keep[wid] = bal;
    }
    if (tid < 8) s_rowmask[tid] = 0;
    float* op = out + (size_t)pair * (TOPK * 5);
    {
        float4* op4 = (float4*)op;
        if (tid < TOPK * 5 / 4) op4[tid] = make_float4(0.f, 0.f, 0.f, 0.f);
    }
    uint32_t* s_supp = (uint32_t*)s_h64;
    __syncthreads();

    // ===== suppression bitmatrix: balanced schedule, FFMA-band IoU =====
#pragma unroll 1
    for (int g = 0; g < 8; g++) {
        const int    colg = g * 32 + lane;
        const float4 bg   = s_box[colg];
        const float  ag   = s_area[colg];
        const float  chi  = __fmul_rn(0.310395f, ag);
        const float  clo  = __fmul_rn(0.310295f, ag);
        const int    gbase = g * 32;
#pragma unroll 1
        for (int t = 0; t < g; t++) {
#pragma unroll
            for (int u = 0; u < 4; u++) {
                const int i = wid + t * 32 + u * 8;
                float4 bi = s_box[i];
                float wx = fmaxf(fminf(bi.z, bg.z) - fmaxf(bi.x, bg.x), 0.f);
                float wy = fmaxf(fminf(bi.w, bg.w) - fmaxf(bi.y, bg.y), 0.f);
                float inter = __fmul_rn(wx, wy);
                float ai = s_area[i];
                bool sup = inter > __fmaf_rn(0.310395f, ai, chi);
                if (!sup && inter >= __fmaf_rn(0.310295f, ai, clo)) {
                    float s  = __fadd_rn(ai, ag);
                    float ut = fmaxf(__fadd_rn(s, -inter), 1e-9f);
                    sup = (inter / ut) > 0.45f;           // exact IEEE path (rare)
                }
                uint32_t bal = __ballot_sync(0xFFFFFFFFu, sup);
                if (lane == 0) {
                    s_supp[i * 8 + g] = bal;
                    if (bal) atomicOr(&s_rowmask[i >> 5], 1u << (i & 31));
                }
            }
        }
#pragma unroll
        for (int t = 0; t < 4; t++) {
            const int i = gbase + wid + t * 8;
            float4 bi = s_box[i];
            float wx = fmaxf(fminf(bi.z, bg.z) - fmaxf(bi.x, bg.x), 0.f);
            float wy = fmaxf(fminf(bi.w, bg.w) - fmaxf(bi.y, bg.y), 0.f);
            float inter = __fmul_rn(wx, wy);
            float ai = s_area[i];
            bool gt  = colg > i;
            bool sup = gt && (inter > __fmaf_rn(0.310395f, ai, chi));
            if (gt && !sup && inter >= __fmaf_rn(0.310295f, ai, clo)) {
                float s  = __fadd_rn(ai, ag);
                float ut = fmaxf(__fadd_rn(s, -inter), 1e-9f);
                sup = (inter / ut) > 0.45f;
            }
            uint32_t bal = __ballot_sync(0xFFFFFFFFu, sup);
            if (lane == 0) {
                s_supp[i * 8 + g] = bal;
                if (bal) atomicOr(&s_rowmask[i >> 5], 1u << (i & 31));
            }
        }
    }
    __syncthreads();

    // ====== sparse greedy scan on warp 0 (only rows that suppress someone) ======
    if (wid == 0) {
        uint32_t kw = (lane < 8) ? s_keep[lane] : 0u;
        for (int w8 = 0; w8 < 8; w8++) {
            uint32_t rm = s_rowmask[w8];
            while (rm) {
                int bit = __ffs(rm) - 1; rm &= rm - 1;
                int i = w8 * 32 + bit;
                uint32_t w = __shfl_sync(0xFFFFFFFFu, kw, w8);
                uint32_t cur = (lane < 8 && lane >= w8) ? s_supp[i * 8 + lane] : 0u;
                if ((w >> bit) & 1u)
                    kw &= ~cur;
            }
        }
        if (lane < 8) s_keep[lane] = kw;
    }
    __syncthreads();

    // ================= compaction + output =================
    if (tid == 0) {
        uint32_t a = 0;
#pragma unroll
        for (int w2 = 0; w2 < 8; w2++) { s_wpre[w2] = a; a += __popc(s_keep[w2]); }
        g_cnt[pair] = 0;   // reset speculative counter for the next launch/replay
    }
    __syncthreads();

    uint32_t kwm = s_keep[wid];
    if ((kwm >> lane) & 1u) {
        uint32_t rank = s_wpre[wid] + __popc(kwm & ((1u << lane) - 1u));
        if (rank < TOPK) {
            float* r = op + (size_t)rank * 5;
            r[0] = scv;
            r[1] = bj.x; r[2] = bj.y; r[3] = bj.z; r[4] = bj.w;
        }
    }
}

// ------------------------------------------------------------------
extern "C" void kernel_launch(void* const* d_in, const int* in_sizes, int n_in,
                              void* d_out, int out_size) {
    const float* loc   = (const float*)d_in[0];
    const float* conf  = (const float*)d_in[1];
    const float* prior = (const float*)d_in[2];
    float* out = (float*)d_out;

    dim3 pgrid((PNUM + 255) / 256, BNUM);
    prep_kernel<<<pgrid, 256>>>(conf);
    topk_nms_kernel<<<NPAIR, NT>>>(out, loc, prior);
}

// round 16
// speedup vs baseline: 2.1209x; 1.0956x over previous
#include <cuda_runtime.h>
#include <stdint.h>

#define BNUM 32
#define PNUM 8732
#define CFG  20
#define NPAIR (BNUM*CFG)
#define KPRE 256
#define TOPK 200
#define CAP  2048
#define QCAP 1024
#define NT   256

typedef unsigned long long u64;

// ------------------------------------------------------------------
__device__ u64      g_list[(size_t)NPAIR * CAP];    // speculative candidate lists
__device__ uint32_t g_cnt[NPAIR];                   // list counters (zeroed by topk epilogue)

__device__ __forceinline__ uint32_t mono(float f) {
    uint32_t u = __float_as_uint(f);
    return (u & 0x80000000u) ? ~u : (u | 0x80000000u);
}
__device__ __forceinline__ float unmono(uint32_t k) {
    uint32_t u = (k & 0x80000000u) ? (k ^ 0x80000000u) : ~k;
    return __uint_as_float(u);
}

// fixed speculative threshold: prob 0.10 (P(key>=T) ~ 10% per pair here;
// any pair outside [KPRE, CAP] takes the exact recompute fallback in topk)
#define T_FIXED 0xBDCCCCCDu   // mono(0.10f)

// exact key recompute (op-for-op identical to prep's softmax) — fallback only
__device__ __noinline__ uint32_t key_of(const float* __restrict__ conf,
                                        int b, int c, int p) {
    const float* cp = conf + ((size_t)b * PNUM + p) * 21;
    float x[21];
#pragma unroll
    for (int i = 0; i < 21; i++) x[i] = cp[i];
    float m = x[0];
#pragma unroll
    for (int i = 1; i < 21; i++) m = fmaxf(m, x[i]);
    float e[21];
    float s = 0.f;
#pragma unroll
    for (int i = 0; i < 21; i++) { e[i] = expf(x[i] - m); s += e[i]; }
    return mono(e[c + 1] / s);
}

// ------------------------------------------------------------------
// kernel 1: softmax (exact jax.nn.softmax order) + speculative push.
//   ONE parallel atomic round per warp: lanes 0..19 reserve space for
//   classes 1..20 concurrently. No key array written.
// ------------------------------------------------------------------
__global__ __launch_bounds__(256) void prep_kernel(const float* __restrict__ conf) {
    const int p    = blockIdx.x * 256 + threadIdx.x;
    const int b    = blockIdx.y;
    const int lane = threadIdx.x & 31;
    const bool in  = p < PNUM;

    // --- softmax (guarded; no early return so warp stays converged) ---
    float e[21];
    float s = 1.f;
    if (in) {
        const float* cp = conf + ((size_t)b * PNUM + p) * 21;
        float x[21];
#pragma unroll
        for (int c = 0; c < 21; c++) x[c] = cp[c];
        float m = x[0];
#pragma unroll
        for (int c = 1; c < 21; c++) m = fmaxf(m, x[c]);
        s = 0.f;
#pragma unroll
        for (int c = 0; c < 21; c++) { e[c] = expf(x[c] - m); s += e[c]; }
    }

    // --- phase 1: keys + ballots (uniform flow) ---
    uint32_t kk[CFG];
    uint32_t bal[CFG];
    bool     q[CFG];
    uint32_t mybal = 0;
#pragma unroll
    for (int c = 0; c < CFG; c++) {
        kk[c] = in ? mono(e[c + 1] / s) : 0u;
        q[c] = in && (kk[c] >= T_FIXED);
        bal[c] = __ballot_sync(0xFFFFFFFFu, q[c]);
        if (lane == c) mybal = bal[c];   // lane c latches class c's ballot
    }

    // --- phase 2: ONE atomic instruction, lanes 0..19, 20 distinct counters ---
    uint32_t base = 0;
    if (lane < CFG && mybal)
        base = atomicAdd(&g_cnt[b * CFG + lane], (uint32_t)__popc(mybal));

    // --- phase 3: scatter (bases broadcast via shfl; uniform flow) ---
    const uint32_t ltmask = (1u << lane) - 1u;
#pragma unroll
    for (int c = 0; c < CFG; c++) {
        uint32_t bc = __shfl_sync(0xFFFFFFFFu, base, c);
        if (q[c]) {
            uint32_t pos = bc + __popc(bal[c] & ltmask);
            if (pos < CAP)
                g_list[(size_t)(b * CFG + c) * CAP + pos] =
                    ((u64)kk[c] << 32) | (uint32_t)(~(uint32_t)p);
        }
    }
}

// ------------------------------------------------------------------
// warp 0 helpers (called by all 32 lanes of warp 0)
// ------------------------------------------------------------------
__device__ __forceinline__ void warp_select(const uint32_t* s_hist,
                                            const uint32_t* s_csum,
                                            uint32_t target, uint32_t n0,
                                            volatile uint32_t* s_sel) {
    const int l = threadIdx.x;
    uint32_t v[8]; uint32_t tot = 0;
#pragma unroll
    for (int m = 0; m < 8; m++) { v[m] = s_csum[l * 8 + m]; tot += v[m]; }
    uint32_t incl = tot;
#pragma unroll
    for (int o = 1; o < 32; o <<= 1) {
        uint32_t t = __shfl_down_sync(0xFFFFFFFFu, incl, o);
        if (l + o < 32) incl += t;
    }
    uint32_t above = incl - tot;
    if ((above + n0 < target) && (incl + n0 >= target)) {
        uint32_t acc = above + n0;
        int mm = 0;
        for (int m = 7; m >= 0; m--) {
            if (acc + v[m] >= target) { mm = m; break; }
            acc += v[m];
        }
        int chunk = l * 8 + mm;
        int bb = chunk * 8;
        for (int bi = chunk * 8 + 7; bi >= chunk * 8; bi--) {
            uint32_t h = s_hist[bi];
            if (acc + h >= target) { bb = bi; break; }
            acc += h;
        }
        s_sel[0] = (uint32_t)bb; s_sel[1] = acc;
    }
}

__device__ __forceinline__ void warp_select256(const uint32_t* s_hist,
                                               uint32_t target, uint32_t n0,
                                               volatile uint32_t* s_sel) {
    const int l = threadIdx.x;
    uint32_t v[8]; uint32_t tot = 0;
#pragma unroll
    for (int m = 0; m < 8; m++) { v[m] = s_hist[l * 8 + m]; tot += v[m]; }
    uint32_t incl = tot;
#pragma unroll
    for (int o = 1; o < 32; o <<= 1) {
        uint32_t t = __shfl_down_sync(0xFFFFFFFFu, incl, o);
        if (l + o < 32) incl += t;
    }
    uint32_t above = incl - tot;
    if ((above + n0 < target) && (incl + n0 >= target)) {
        uint32_t acc = above + n0;
        int bb = l * 8;
        for (int m = 7; m >= 0; m--) {
            if (acc + v[m] >= target) { bb = l * 8 + m; break; }
            acc += v[m];
        }
        s_sel[0] = (uint32_t)bb; s_sel[1] = acc;
    }
}

// ------------------------------------------------------------------
// kernel 2: per (b,c) pair
// ------------------------------------------------------------------
__global__ __launch_bounds__(NT) void topk_nms_kernel(float* __restrict__ out,
                                                      const float* __restrict__ loc,
                                                      const float* __restrict__ prior,
                                                      const float* __restrict__ conf) {
    __shared__ u64      s_h64[1024];     // hist(2048 u32) / compacted / supp matrix
    __shared__ uint32_t s_csum[256];
    __shared__ u64      s_cand[CAP];
    __shared__ u64      s_key[KPRE];
    __shared__ float4   s_box[KPRE];
    __shared__ float    s_area[KPRE];
    __shared__ uint32_t s_keep[8];
    __shared__ uint32_t s_wpre[8];
    __shared__ uint32_t s_rowmask[8];
    __shared__ uint32_t s_sel[2];
    __shared__ uint32_t s_cnt;
    uint32_t* s_hist = (uint32_t*)s_h64;

    const int pair = blockIdx.x;
    const int b    = pair / CFG;
    const int cc   = pair % CFG;
    const int tid  = threadIdx.x;
    const int wid  = tid >> 5, lane = tid & 31;

    // ============ candidate set: speculative list from prep (fast path) ============
    uint32_t M = g_cnt[pair];
    if (M >= KPRE && M <= CAP) {
        const u64* __restrict__ lst = g_list + (size_t)pair * CAP;
        for (uint32_t i = tid; i < M; i += NT) s_cand[i] = lst[i];
        __syncthreads();
    } else {
        // ====== exact fallback: recompute keys from conf (rare / adversarial) ======
        {
            uint4* hz = (uint4*)s_hist;
            hz[tid] = make_uint4(0, 0, 0, 0);
            hz[tid + 256] = make_uint4(0, 0, 0, 0);
        }
        __syncthreads();
        for (int p = tid; p < PNUM; p += NT)
            atomicAdd(&s_hist[key_of(conf, b, cc, p) >> 21], 1u);
        __syncthreads();
        {
            uint32_t cs = 0;
#pragma unroll
            for (int i = 0; i < 8; i++) cs += s_hist[tid * 8 + i];
            s_csum[tid] = cs;
        }
        __syncthreads();
        if (wid == 0) warp_select(s_hist, s_csum, KPRE, 0, s_sel);
        __syncthreads();
        uint32_t bbe = s_sel[0], n_above = s_sel[1];
        uint32_t Te = bbe << 21;
        if (tid == 0) s_cnt = 0;
        __syncthreads();
        for (int p = tid; p < PNUM; p += NT) {
            uint32_t k = key_of(conf, b, cc, p);
            if (k >= Te) {
                uint32_t pos = atomicAdd(&s_cnt, 1u);
                if (pos < CAP) s_cand[pos] = ((u64)k << 32) | (uint32_t)(~(uint32_t)p);
            }
        }
        __syncthreads();
        M = s_cnt;
        if (M > CAP) {   // boundary bin too fat: refine to 21 bits
            for (int i = tid; i < 2048; i += NT) s_hist[i] = 0;
            __syncthreads();
            for (int p = tid; p < PNUM; p += NT) {
                uint32_t k = key_of(conf, b, cc, p);
                if ((k >> 21) == bbe) atomicAdd(&s_hist[(k >> 10) & 0x7FFu], 1u);
            }
            __syncthreads();
            {
                uint32_t cs = 0;
#pragma unroll
                for (int i = 0; i < 8; i++) cs += s_hist[tid * 8 + i];
                s_csum[tid] = cs;
            }
            __syncthreads();
            if (wid == 0) warp_select(s_hist, s_csum, KPRE, n_above, s_sel);
            __syncthreads();
            uint32_t pref21 = (bbe << 11) | s_sel[0];
            if (tid == 0) s_cnt = 0;
            __syncthreads();
            for (int p = tid; p < PNUM; p += NT) {
                uint32_t k = key_of(conf, b, cc, p);
                if ((k >> 10) >= pref21) {
                    uint32_t pos = atomicAdd(&s_cnt, 1u);
                    if (pos < CAP) s_cand[pos] = ((u64)k << 32) | (uint32_t)(~(uint32_t)p);
                }
            }
            __syncthreads();
            M = s_cnt;
            if (M > CAP) M = CAP;
        }
    }

    // ============ in-shared refine, 4 levels x 8-bit digits -> exact F ============
    uint32_t pref = 0, n0 = 0;
#pragma unroll
    for (int lev = 0; lev < 4; lev++) {
        const int sh = 24 - lev * 8;
        if (tid < 256) s_hist[tid] = 0;
        __syncthreads();
        for (uint32_t i = tid; i < M; i += NT) {
            uint32_t k = (uint32_t)(s_cand[i] >> 32);
            bool match = (lev == 0) || ((k >> (sh + 8)) == pref);
            if (match) atomicAdd(&s_hist[(k >> sh) & 255u], 1u);
        }
        __syncthreads();
        if (wid == 0) warp_select256(s_hist, KPRE, n0, s_sel);
        __syncthreads();
        pref = (pref << 8) | s_sel[0];
        n0 = s_sel[1];
        __syncthreads();
    }
    const uint32_t F = pref;

    // ================= compact qualifying (key >= F) =================
    if (tid == 0) s_cnt = 0;
    __syncthreads();
    for (uint32_t i = tid; i < M; i += NT) {
        u64 c = s_cand[i];
        if ((uint32_t)(c >> 32) >= F) {
            uint32_t pos = atomicAdd(&s_cnt, 1u);
            if (pos < QCAP) s_h64[pos] = c;
        }
    }
    __syncthreads();
    uint32_t M2 = s_cnt; if (M2 > QCAP) M2 = QCAP;

    // ================= sort: bitonic-256 (generic) or rank-sort (ties) =================
    if (M2 == KPRE) {
        u64 mine = s_h64[tid];
        __syncthreads();
#pragma unroll
        for (uint32_t k = 2; k <= 256; k <<= 1) {
            for (uint32_t j = k >> 1; j >= 1; j >>= 1) {
                u64 other;
                if (j >= 32) {
                    s_key[tid] = mine;
                    __syncthreads();
                    other = s_key[tid ^ j];
                    __syncthreads();
                } else {
                    other = __shfl_xor_sync(0xFFFFFFFFu, mine, j);
                }
                bool lower   = (tid & j) == 0;
                bool dirDesc = (tid & k) == 0;
                bool takeMax = (lower == dirDesc);
                u64 mx = mine > other ? mine : other;
                u64 mn = mine > other ? other : mine;
                mine = takeMax ? mx : mn;
            }
        }
        s_key[tid] = mine;
    } else {
        for (uint32_t i = tid; i < M2; i += NT) {
            u64 mine = s_h64[i];
            uint32_t rank = 0;
            for (uint32_t j = 0; j < M2; j++) rank += (s_h64[j] > mine);
            if (rank < KPRE) s_key[rank] = mine;
        }
    }
    __syncthreads();

    // ======== extract top-256: decode box on demand (exact prep arithmetic) ========
    u64 key = s_key[tid];
    uint32_t idx = ~(uint32_t)key;
    float scv = unmono((uint32_t)(key >> 32));
    float4 bj;
    {
        float4 l  = __ldg((const float4*)loc + (size_t)b * PNUM + idx);
        float4 pr = __ldg((const float4*)prior + idx);
        float cx = pr.x + (l.x * 0.1f) * pr.z;
        float cy = pr.y + (l.y * 0.1f) * pr.w;
        float w  = pr.z * expf(l.z * 0.2f);
        float h  = pr.w * expf(l.w * 0.2f);
        float x1 = cx - w * 0.5f;
        float y1 = cy - h * 0.5f;
        bj = make_float4(x1, y1, x1 + w, y1 + h);
    }
    float aj = fmaxf(bj.z - bj.x, 0.f) * fmaxf(bj.w - bj.y, 0.f);
    s_box[tid]  = bj;
    s_area[tid] = aj;
    {
        bool valid = scv > 0.01f;
        uint32_t bal = __ballot_sync(0xFFFFFFFFu, valid);
        if (lane == 0) s_keep[wid] = bal;
    }
    if (tid < 8) s_rowmask[tid] = 0;
    float* op = out + (size_t)pair * (TOPK * 5);
    {
        float4* op4 = (float4*)op;
        if (tid < TOPK * 5 / 4) op4[tid] = make_float4(0.f, 0.f, 0.f, 0.f);
    }
    uint32_t* s_supp = (uint32_t*)s_h64;
    __syncthreads();

    // ===== suppression bitmatrix: balanced schedule, FFMA-band IoU =====
#pragma unroll 1
    for (int g = 0; g < 8; g++) {
        const int    colg = g * 32 + lane;
        const float4 bg   = s_box[colg];
        const float  ag   = s_area[colg];
        const float  chi  = __fmul_rn(0.310395f, ag);
        const float  clo  = __fmul_rn(0.310295f, ag);
        const int    gbase = g * 32;
#pragma unroll 1
        for (int t = 0; t < g; t++) {
#pragma unroll
            for (int u = 0; u < 4; u++) {
                const int i = wid + t * 32 + u * 8;
                float4 bi = s_box[i];
                float wx = fmaxf(fminf(bi.z, bg.z) - fmaxf(bi.x, bg.x), 0.f);
                float wy = fmaxf(fminf(bi.w, bg.w) - fmaxf(bi.y, bg.y), 0.f);
                float inter = __fmul_rn(wx, wy);
                float ai = s_area[i];
                bool sup = inter > __fmaf_rn(0.310395f, ai, chi);
                if (!sup && inter >= __fmaf_rn(0.310295f, ai, clo)) {
                    float s  = __fadd_rn(ai, ag);
                    float ut = fmaxf(__fadd_rn(s, -inter), 1e-9f);
                    sup = (inter / ut) > 0.45f;           // exact IEEE path (rare)
                }
                uint32_t bal = __ballot_sync(0xFFFFFFFFu, sup);
                if (lane == 0) {
                    s_supp[i * 8 + g] = bal;
                    if (bal) atomicOr(&s_rowmask[i >> 5], 1u << (i & 31));
                }
            }
        }
#pragma unroll
        for (int t = 0; t < 4; t++) {
            const int i = gbase + wid + t * 8;
            float4 bi = s_box[i];
            float wx = fmaxf(fminf(bi.z, bg.z) - fmaxf(bi.x, bg.x), 0.f);
            float wy = fmaxf(fminf(bi.w, bg.w) - fmaxf(bi.y, bg.y), 0.f);
            float inter = __fmul_rn(wx, wy);
            float ai = s_area[i];
            bool gt  = colg > i;
            bool sup = gt && (inter > __fmaf_rn(0.310395f, ai, chi));
            if (gt && !sup && inter >= __fmaf_rn(0.310295f, ai, clo)) {
                float s  = __fadd_rn(ai, ag);
                float ut = fmaxf(__fadd_rn(s, -inter), 1e-9f);
                sup = (inter / ut) > 0.45f;
            }
            uint32_t bal = __ballot_sync(0xFFFFFFFFu, sup);
            if (lane == 0) {
                s_supp[i * 8 + g] = bal;
                if (bal) atomicOr(&s_rowmask[i >> 5], 1u << (i & 31));
            }
        }
    }
    __syncthreads();

    // ====== sparse greedy scan on warp 0 (only rows that suppress someone) ======
    if (wid == 0) {
        uint32_t kw = (lane < 8) ? s_keep[lane] : 0u;
        for (int w8 = 0; w8 < 8; w8++) {
            uint32_t rm = s_rowmask[w8];
            while (rm) {
                int bit = __ffs(rm) - 1; rm &= rm - 1;
                int i = w8 * 32 + bit;
                uint32_t w = __shfl_sync(0xFFFFFFFFu, kw, w8);
                uint32_t cur = (lane < 8 && lane >= w8) ? s_supp[i * 8 + lane] : 0u;
                if ((w >> bit) & 1u)
                    kw &= ~cur;
            }
        }
        if (lane < 8) s_keep[lane] = kw;
    }
    __syncthreads();

    // ================= compaction + output =================
    if (tid == 0) {
        uint32_t a = 0;
#pragma unroll
        for (int w2 = 0; w2 < 8; w2++) { s_wpre[w2] = a; a += __popc(s_keep[w2]); }
        g_cnt[pair] = 0;   // reset speculative counter for the next launch/replay
    }
    __syncthreads();

    uint32_t kwm = s_keep[wid];
    if ((kwm >> lane) & 1u) {
        uint32_t rank = s_wpre[wid] + __popc(kwm & ((1u << lane) - 1u));
        if (rank < TOPK) {
            float* r = op + (size_t)rank * 5;
            r[0] = scv;
            r[1] = bj.x; r[2] = bj.y; r[3] = bj.z; r[4] = bj.w;
        }
    }
}

// ------------------------------------------------------------------
extern "C" void kernel_launch(void* const* d_in, const int* in_sizes, int n_in,
                              void* d_out, int out_size) {
    const float* loc   = (const float*)d_in[0];
    const float* conf  = (const float*)d_in[1];
    const float* prior = (const float*)d_in[2];
    float* out = (float*)d_out;

    dim3 pgrid((PNUM + 255) / 256, BNUM);
    prep_kernel<<<pgrid, 256>>>(conf);
    topk_nms_kernel<<<NPAIR, NT>>>(out, loc, prior, conf);
}